// round 10
// baseline (speedup 1.0000x reference)
#include <cuda_runtime.h>

#define NC 18
#define CS 4
#define CH 72
#define NP 4096
#define LOG2E 1.44269504088896340736f

typedef unsigned long long ull;

// Scratch (no allocations allowed): __device__ globals (~94 MB).
__device__ float g_qcT[NC][CS][NP];        // chunk q transposed, pre-scaled log2e/64
__device__ float g_kcT[NC][CS][NP];        // chunk k (raw)
__device__ float g_vcT[NC][CS][NP];        // becomes v/Z after k_zapply
__device__ float g_qg[NP][CH];             // global q, pre-scaled log2e/64
__device__ float g_kg[NP][CH];
__device__ float g_vg[NP][CH];             // becomes v/Z after k_rowsum_fold
__device__ float g_WT[3][CH][CH];          // transposed global weights [c][o]
__device__ float g_E[NP][NP];              // exp2 global scores e[j][i]
__device__ float g_outGPart[16][NP][CH];   // j-segment partials of global output
__device__ float g_outG[NP][CH];           // reduced global output
__device__ float g_Apart[16][NC][34];      // k-moment partials (coeff-folded)
__device__ float g_Bpart[8][NC][CS][35];   // v-weighted q-moment partials

// exp2(x) ~ 1 + L1 x + L2 x^2 + L3 x^3; coefficients with symmetry multiplicities
// folded in, ordered: deg1 (4), deg2 pairs a<=b (10), deg3 triples a<=b<=c (20).
#define L1C 0.6931471805599453f
#define L2C 0.2402265069591007f
#define L3C 0.05550410866482158f
__constant__ float c_coef[34] = {
    L1C, L1C, L1C, L1C,
    L2C, 2*L2C, 2*L2C, 2*L2C, L2C, 2*L2C, 2*L2C, L2C, 2*L2C, L2C,
    L3C, 3*L3C, 3*L3C, 3*L3C, 3*L3C, 6*L3C, 6*L3C, 3*L3C, 6*L3C, 3*L3C,
    L3C, 3*L3C, 3*L3C, 3*L3C, 6*L3C, 3*L3C, L3C, 3*L3C, 3*L3C, L3C};

__device__ __forceinline__ float fexp2(float x) {
    float r; asm("ex2.approx.f32 %0, %1;" : "=f"(r) : "f"(x)); return r;
}
__device__ __forceinline__ ull pfma(ull a, ull b, ull c) {
    ull d; asm("fma.rn.f32x2 %0, %1, %2, %3;" : "=l"(d) : "l"(a), "l"(b), "l"(c)); return d;
}
__device__ __forceinline__ ull padd(ull a, ull b) {
    ull d; asm("add.rn.f32x2 %0, %1, %2;" : "=l"(d) : "l"(a), "l"(b)); return d;
}
__device__ __forceinline__ ull pack2(float lo, float hi) {
    ull d; asm("mov.b64 %0, {%1, %2};" : "=l"(d) : "f"(lo), "f"(hi)); return d;
}
__device__ __forceinline__ float2 unpack2(ull v) {
    float2 f; asm("mov.b64 {%0, %1}, %2;" : "=f"(f.x), "=f"(f.y) : "l"(v)); return f;
}

// Degree-1/2/3 monomials of a 4-vector, in the c_coef ordering.
__device__ __forceinline__ void build_mono(const float q[4], float m[34]) {
#pragma unroll
    for (int c = 0; c < 4; c++) m[c] = q[c];
    int p = 4;
#pragma unroll
    for (int a = 0; a < 4; a++)
#pragma unroll
        for (int b = a; b < 4; b++) m[p++] = q[a] * q[b];
#pragma unroll
    for (int a = 0; a < 4; a++)
#pragma unroll
        for (int b = a; b < 4; b++)
#pragma unroll
            for (int c = b; c < 4; c++) m[p++] = q[a] * q[b] * q[c];
}

// ---------------------------------------------------------------------------
__global__ void k_transpose_W(const float* __restrict__ WqG,
                              const float* __restrict__ WkG,
                              const float* __restrict__ WvG) {
    for (int idx = threadIdx.x; idx < CH * CH; idx += blockDim.x) {
        int o = idx / CH, c = idx % CH;
        g_WT[0][c][o] = WqG[o * CH + c];
        g_WT[1][c][o] = WkG[o * CH + c];
        g_WT[2][c][o] = WvG[o * CH + c];
    }
}

// ---------------------------------------------------------------------------
// Per-chunk projections + fused k-moment partial reduction (k is in regs).
__global__ void k_proj_chunk(const float* __restrict__ x,
                             const float* __restrict__ Wq, const float* __restrict__ bq,
                             const float* __restrict__ Wk, const float* __restrict__ bk,
                             const float* __restrict__ Wv, const float* __restrict__ bv) {
    int n = blockIdx.y;
    int p = blockIdx.x * 256 + threadIdx.x;
    float xv[CS];
#pragma unroll
    for (int c = 0; c < CS; c++) xv[c] = x[(n * CS + c) * NP + p];
    float q[CS], k[CS], v[CS];
#pragma unroll
    for (int o = 0; o < CS; o++) {
        float aq = bq[n * CS + o], ak = bk[n * CS + o], av = bv[n * CS + o];
#pragma unroll
        for (int c = 0; c < CS; c++) {
            aq += Wq[(n * CS + o) * CS + c] * xv[c];
            ak += Wk[(n * CS + o) * CS + c] * xv[c];
            av += Wv[(n * CS + o) * CS + c] * xv[c];
        }
        q[o] = aq * (LOG2E / 64.0f);
        k[o] = ak;
        v[o] = av;
    }
#pragma unroll
    for (int o = 0; o < CS; o++) {
        g_qcT[n][o][p] = q[o];
        g_kcT[n][o][p] = k[o];
        g_vcT[n][o][p] = v[o];
    }
    // fused momK: block-reduce mono(k) -> g_Apart[blockIdx.x][n][.]
    float m[34];
    build_mono(k, m);
#pragma unroll
    for (int pp = 0; pp < 34; pp++)
#pragma unroll
        for (int off = 16; off; off >>= 1)
            m[pp] += __shfl_down_sync(0xffffffffu, m[pp], off);
    __shared__ float red[8][34];
    int w = threadIdx.x >> 5, l = threadIdx.x & 31;
    if (l == 0)
#pragma unroll
        for (int pp = 0; pp < 34; pp++) red[w][pp] = m[pp];
    __syncthreads();
    if (threadIdx.x < 34) {
        float s = 0.f;
#pragma unroll
        for (int w2 = 0; w2 < 8; w2++) s += red[w2][threadIdx.x];
        g_Apart[blockIdx.x][n][threadIdx.x] = s * c_coef[threadIdx.x];
    }
}

// ---------------------------------------------------------------------------
// Global 72-ch projection, register-tiled: thread = (o, 4 p's), x tile in smem.
__global__ void k_proj_global(const float* __restrict__ x,
                              const float* __restrict__ bqG,
                              const float* __restrict__ bkG,
                              const float* __restrict__ bvG) {
    __shared__ __align__(16) float xs[CH][16];
    int o = threadIdx.x;        // 0..71
    int pg = threadIdx.y;       // 0..3
    int p0 = blockIdx.x * 16;
    int tid = threadIdx.x + 72 * threadIdx.y;
    {
        int c = tid >> 2, pp4 = (tid & 3) * 4;
        *(float4*)&xs[c][pp4] = *(const float4*)&x[c * NP + p0 + pp4];
    }
    __syncthreads();
    float aq[4], ak[4], av[4];
    float bqv = bqG[o], bkv = bkG[o], bvv = bvG[o];
#pragma unroll
    for (int t = 0; t < 4; t++) { aq[t] = bqv; ak[t] = bkv; av[t] = bvv; }
    for (int c = 0; c < CH; c++) {
        float wq = g_WT[0][c][o], wk = g_WT[1][c][o], wv = g_WT[2][c][o];
        float4 xv4 = *(const float4*)&xs[c][pg * 4];
        aq[0] += wq * xv4.x; aq[1] += wq * xv4.y; aq[2] += wq * xv4.z; aq[3] += wq * xv4.w;
        ak[0] += wk * xv4.x; ak[1] += wk * xv4.y; ak[2] += wk * xv4.z; ak[3] += wk * xv4.w;
        av[0] += wv * xv4.x; av[1] += wv * xv4.y; av[2] += wv * xv4.z; av[3] += wv * xv4.w;
    }
#pragma unroll
    for (int t = 0; t < 4; t++) {
        int p = p0 + pg * 4 + t;
        g_qg[p][o] = aq[t] * (LOG2E / 64.0f);
        g_kg[p][o] = ak[t];
        g_vg[p][o] = av[t];
    }
}

// ---------------------------------------------------------------------------
// Z_j = N + mono(qs_j) . A (sum of 16 partials);  fold 1/Z into v (stored).
__global__ void k_zapply() {
    __shared__ float As[34];
    int n = blockIdx.y;
    int j = blockIdx.x * 256 + threadIdx.x;
    if (threadIdx.x < 34) {
        float s = 0.f;
#pragma unroll
        for (int sg = 0; sg < 16; sg++) s += g_Apart[sg][n][threadIdx.x];
        As[threadIdx.x] = s;
    }
    __syncthreads();
    float q[4];
#pragma unroll
    for (int c = 0; c < 4; c++) q[c] = g_qcT[n][c][j];
    float m[34];
    build_mono(q, m);
    float z = (float)NP;
#pragma unroll
    for (int p = 0; p < 34; p++) z += m[p] * As[p];
    float rz = 1.0f / z;
#pragma unroll
    for (int c = 0; c < 4; c++) g_vcT[n][c][j] *= rz;
}

// ---------------------------------------------------------------------------
// v-weighted q-moment partials: grid (18 chunks, 8 j-segments of 512).
__global__ void k_momVQ() {
    int n = blockIdx.x, seg = blockIdx.y;
    int c = threadIdx.x & 3;
    float acc[35];
#pragma unroll
    for (int p = 0; p < 35; p++) acc[p] = 0.f;
    for (int j = seg * 512 + (threadIdx.x >> 2); j < seg * 512 + 512; j += 64) {
        float q[4];
#pragma unroll
        for (int cc = 0; cc < 4; cc++) q[cc] = g_qcT[n][cc][j];
        float m[34];
        build_mono(q, m);
        float v = g_vcT[n][c][j];
        acc[0] += v;
#pragma unroll
        for (int p = 0; p < 34; p++) acc[1 + p] += v * m[p];
    }
#pragma unroll
    for (int p = 0; p < 35; p++)
#pragma unroll
        for (int off = 16; off >= 4; off >>= 1)
            acc[p] += __shfl_down_sync(0xffffffffu, acc[p], off);
    __shared__ float red[8][4][35];
    int w = threadIdx.x >> 5, l = threadIdx.x & 31;
    if (l < 4)
#pragma unroll
        for (int p = 0; p < 35; p++) red[w][l][p] = acc[p];
    __syncthreads();
    if (threadIdx.x < 140) {
        int cc = threadIdx.x / 35, p = threadIdx.x % 35;
        float s = 0.f;
#pragma unroll
        for (int w2 = 0; w2 < 8; w2++) s += red[w2][cc][p];
        g_Bpart[seg][n][cc][p] = s;
    }
}

// ---------------------------------------------------------------------------
// Global scores computed ONCE: E[j][i] = exp2(q_j . k_i). i-threaded (coalesced
// stores), q tiles in smem. Grid (32 i-blocks, 16 j-segments of 256).
__global__ void __launch_bounds__(128) k_score() {
    __shared__ __align__(16) float q_s[64][CH];
    int i = blockIdx.x * 128 + threadIdx.x;
    int seg = blockIdx.y;
    ull kk2[CH / 2];
    const ulonglong2* krow = (const ulonglong2*)&g_kg[i][0];
#pragma unroll
    for (int c = 0; c < CH / 4; c++) { ulonglong2 t = krow[c]; kk2[2 * c] = t.x; kk2[2 * c + 1] = t.y; }
    for (int jt = 0; jt < 4; jt++) {
        int j0 = seg * 256 + jt * 64;
        const float4* qsrc = (const float4*)&g_qg[j0][0];
        float4* qdst = (float4*)&q_s[0][0];
        for (int r = threadIdx.x; r < 64 * CH / 4; r += 128) qdst[r] = qsrc[r];
        __syncthreads();
#pragma unroll 2
        for (int j = 0; j < 64; j++) {
            const ulonglong2* qr = (const ulonglong2*)&q_s[j][0];
            ull s0 = 0, s1 = 0, s2 = 0, s3 = 0;
#pragma unroll
            for (int c = 0; c < CH / 4; c += 2) {
                ulonglong2 t0 = qr[c], t1 = qr[c + 1];
                s0 = pfma(kk2[2 * c], t0.x, s0);     s1 = pfma(kk2[2 * c + 1], t0.y, s1);
                s2 = pfma(kk2[2 * c + 2], t1.x, s2); s3 = pfma(kk2[2 * c + 3], t1.y, s3);
            }
            float2 sf = unpack2(padd(padd(s0, s1), padd(s2, s3)));
            g_E[j0 + j][i] = fexp2(sf.x + sf.y);
        }
        __syncthreads();
    }
}

// ---------------------------------------------------------------------------
// Row-sum E -> Z_j, fold 1/Z into vg. Warp per row, 8 rows per block.
__global__ void k_rowsum_fold() {
    int w = threadIdx.x >> 5, l = threadIdx.x & 31;
    int j = blockIdx.x * 8 + w;
    float z = 0.f;
    for (int t = l; t < NP / 4; t += 32) {
        float4 e4 = *(const float4*)&g_E[j][t * 4];
        z += (e4.x + e4.y) + (e4.z + e4.w);
    }
#pragma unroll
    for (int off = 16; off; off >>= 1) z += __shfl_down_sync(0xffffffffu, z, off);
    float rz = __shfl_sync(0xffffffffu, 1.0f / z, 0);
    if (l < CH / 4) {
        float4 v = *(float4*)&g_vg[j][l * 4];
        v.x *= rz; v.y *= rz; v.z *= rz; v.w *= rz;
        *(float4*)&g_vg[j][l * 4] = v;
    }
}

// ---------------------------------------------------------------------------
// Global pass 2 with memoized scores: out[c,i] += sum_{j in seg} v'[c,j]*E[j][i].
__global__ void __launch_bounds__(128) k_og2() {
    __shared__ __align__(16) float v_s[64][CH];
    int i = blockIdx.x * 128 + threadIdx.x;
    int seg = blockIdx.y;  // 0..15 -> j in [seg*256, +256)
    ull out2[CH / 2];
#pragma unroll
    for (int c = 0; c < CH / 2; c++) out2[c] = 0;
    for (int jt = 0; jt < 4; jt++) {
        int j0 = seg * 256 + jt * 64;
        const float4* vsrc = (const float4*)&g_vg[j0][0];
        float4* vdst = (float4*)&v_s[0][0];
        for (int r = threadIdx.x; r < 64 * CH / 4; r += 128) vdst[r] = vsrc[r];
        __syncthreads();
#pragma unroll 2
        for (int j = 0; j < 64; j++) {
            float e = __ldg(&g_E[j0 + j][i]);
            ull ee = pack2(e, e);
            const ulonglong2* vr = (const ulonglong2*)&v_s[j][0];
#pragma unroll
            for (int c = 0; c < CH / 4; c++) {
                ulonglong2 t = vr[c];
                out2[2 * c] = pfma(t.x, ee, out2[2 * c]);
                out2[2 * c + 1] = pfma(t.y, ee, out2[2 * c + 1]);
            }
        }
        __syncthreads();
    }
#pragma unroll
    for (int c = 0; c < CH / 4; c++) {
        float2 a = unpack2(out2[2 * c]), b = unpack2(out2[2 * c + 1]);
        *(float4*)&g_outGPart[seg][i][4 * c] = make_float4(a.x, a.y, b.x, b.y);
    }
}

// ---------------------------------------------------------------------------
// Reduce 16 outGPart segments once: g_outG[i][c] = sum_s g_outGPart[s][i][c].
__global__ void k_gred() {
    int idx = blockIdx.x * 256 + threadIdx.x;  // float4 index, 73728 total
    int i = idx / (CH / 4), c4 = (idx % (CH / 4)) * 4;
    float4 a = *(const float4*)&g_outGPart[0][i][c4];
#pragma unroll
    for (int s = 1; s < 16; s++) {
        float4 b = *(const float4*)&g_outGPart[s][i][c4];
        a.x += b.x; a.y += b.y; a.z += b.z; a.w += b.w;
    }
    *(float4*)&g_outG[i][c4] = a;
}

// ---------------------------------------------------------------------------
// Chunk pass 2 via B-moments + reduced global output + pooled reduction.
__global__ void k_apply(const float* __restrict__ x, float* __restrict__ out) {
    __shared__ float Bs[4][35];
    int n = blockIdx.y;
    int i = blockIdx.x * 256 + threadIdx.x;
    if (threadIdx.x < 140) {
        int cc = threadIdx.x / 35, p = threadIdx.x % 35;
        float s = 0.f;
#pragma unroll
        for (int sg = 0; sg < 8; sg++) s += g_Bpart[sg][n][cc][p];
        Bs[cc][p] = s;
    }
    __syncthreads();
    float k[4];
#pragma unroll
    for (int c = 0; c < 4; c++) k[c] = g_kcT[n][c][i];
    float m[34];
    build_mono(k, m);
#pragma unroll
    for (int p = 0; p < 34; p++) m[p] *= c_coef[p];
    float a[4];
#pragma unroll
    for (int c = 0; c < 4; c++) {
        float s = Bs[c][0];
#pragma unroll
        for (int p = 0; p < 34; p++) s += m[p] * Bs[c][1 + p];
        a[c] = s;
    }
    float4 og = *(const float4*)&g_outG[i][n * 4];
    a[0] += og.x; a[1] += og.y; a[2] += og.z; a[3] += og.w;
    float p = a[0] * x[(n * 4 + 0) * NP + i] + a[1] * x[(n * 4 + 1) * NP + i] +
              a[2] * x[(n * 4 + 2) * NP + i] + a[3] * x[(n * 4 + 3) * NP + i];
    out[n * NP + i] = p;
}

// ---------------------------------------------------------------------------
extern "C" void kernel_launch(void* const* d_in, const int* in_sizes, int n_in,
                              void* d_out, int out_size) {
    const float* x   = (const float*)d_in[0];
    const float* Wq  = (const float*)d_in[1];
    const float* bq  = (const float*)d_in[2];
    const float* Wk  = (const float*)d_in[3];
    const float* bk  = (const float*)d_in[4];
    const float* Wv  = (const float*)d_in[5];
    const float* bv  = (const float*)d_in[6];
    const float* WqG = (const float*)d_in[7];
    const float* bqG = (const float*)d_in[8];
    const float* WkG = (const float*)d_in[9];
    const float* bkG = (const float*)d_in[10];
    const float* WvG = (const float*)d_in[11];
    const float* bvG = (const float*)d_in[12];
    float* out = (float*)d_out;

    k_transpose_W<<<1, 512>>>(WqG, WkG, WvG);
    k_proj_chunk<<<dim3(16, 18), 256>>>(x, Wq, bq, Wk, bk, Wv, bv);
    k_proj_global<<<256, dim3(72, 4)>>>(x, bqG, bkG, bvG);
    k_zapply<<<dim3(16, 18), 256>>>();
    k_momVQ<<<dim3(18, 8), 256>>>();
    k_score<<<dim3(32, 16), 128>>>();
    k_rowsum_fold<<<512, 256>>>();
    k_og2<<<dim3(32, 16), 128>>>();
    k_gred<<<288, 256>>>();
    k_apply<<<dim3(16, 18), 256>>>(x, out);
}

// round 11
// speedup vs baseline: 1.0840x; 1.0840x over previous
#include <cuda_runtime.h>

#define NC 18
#define CS 4
#define CH 72
#define NP 4096
#define LOG2E 1.44269504088896340736f

typedef unsigned long long ull;

// Scratch (no allocations allowed): __device__ globals (~94 MB).
__device__ float g_qcT[NC][CS][NP];        // chunk q transposed, pre-scaled log2e/64
__device__ float g_kcT[NC][CS][NP];        // chunk k (raw)
__device__ float g_vcT[NC][CS][NP];        // chunk v (raw; 1/Z folded in regs)
__device__ float g_qg[NP][CH];             // global q, pre-scaled log2e/64
__device__ float g_kg[NP][CH];
__device__ float g_vg[NP][CH];             // becomes v/Z after k_rowsum_fold
__device__ float g_E[NP][NP];              // exp2 global scores e[j][i]
__device__ float g_outGPart[16][NP][CH];   // j-segment partials of global output
__device__ float g_Apart[16][NC][34];      // k-moment partials (coeff-folded)
__device__ float g_Bpart[8][NC][CS][35];   // v-weighted q-moment partials

#define L1C 0.6931471805599453f
#define L2C 0.2402265069591007f
#define L3C 0.05550410866482158f
__constant__ float c_coef[34] = {
    L1C, L1C, L1C, L1C,
    L2C, 2*L2C, 2*L2C, 2*L2C, L2C, 2*L2C, 2*L2C, L2C, 2*L2C, L2C,
    L3C, 3*L3C, 3*L3C, 3*L3C, 3*L3C, 6*L3C, 6*L3C, 3*L3C, 6*L3C, 3*L3C,
    L3C, 3*L3C, 3*L3C, 3*L3C, 6*L3C, 3*L3C, L3C, 3*L3C, 3*L3C, L3C};

__device__ __forceinline__ float fexp2(float x) {
    float r; asm("ex2.approx.f32 %0, %1;" : "=f"(r) : "f"(x)); return r;
}
__device__ __forceinline__ ull pfma(ull a, ull b, ull c) {
    ull d; asm("fma.rn.f32x2 %0, %1, %2, %3;" : "=l"(d) : "l"(a), "l"(b), "l"(c)); return d;
}
__device__ __forceinline__ ull padd(ull a, ull b) {
    ull d; asm("add.rn.f32x2 %0, %1, %2;" : "=l"(d) : "l"(a), "l"(b)); return d;
}
__device__ __forceinline__ ull pack2(float lo, float hi) {
    ull d; asm("mov.b64 %0, {%1, %2};" : "=l"(d) : "f"(lo), "f"(hi)); return d;
}
__device__ __forceinline__ float2 unpack2(ull v) {
    float2 f; asm("mov.b64 {%0, %1}, %2;" : "=f"(f.x), "=f"(f.y) : "l"(v)); return f;
}

__device__ __forceinline__ void build_mono(const float q[4], float m[34]) {
#pragma unroll
    for (int c = 0; c < 4; c++) m[c] = q[c];
    int p = 4;
#pragma unroll
    for (int a = 0; a < 4; a++)
#pragma unroll
        for (int b = a; b < 4; b++) m[p++] = q[a] * q[b];
#pragma unroll
    for (int a = 0; a < 4; a++)
#pragma unroll
        for (int b = a; b < 4; b++)
#pragma unroll
            for (int c = b; c < 4; c++) m[p++] = q[a] * q[b] * q[c];
}

// ---------------------------------------------------------------------------
// STAGE 1 (288 threads): blocks [0,288) chunk projections + k-moment partials;
// blocks [288,544) global 72-ch projection with in-block W transpose (dyn smem).
__global__ void k_stage1(const float* __restrict__ x,
                         const float* __restrict__ Wq, const float* __restrict__ bq,
                         const float* __restrict__ Wk, const float* __restrict__ bk,
                         const float* __restrict__ Wv, const float* __restrict__ bv,
                         const float* __restrict__ WqG, const float* __restrict__ bqG,
                         const float* __restrict__ WkG, const float* __restrict__ bkG,
                         const float* __restrict__ WvG, const float* __restrict__ bvG) {
    extern __shared__ float dyn[];
    int bid = blockIdx.x;
    int tid = threadIdx.x;  // 0..287
    if (bid < 288) {
        // ---- proj_chunk role (threads 0..255 active; 256..287 idle thru barrier)
        int bx = bid & 15, n = bid >> 4;
        __shared__ float red[8][34];
        float m[34];
        if (tid < 256) {
            int p = bx * 256 + tid;
            float xv[CS];
#pragma unroll
            for (int c = 0; c < CS; c++) xv[c] = x[(n * CS + c) * NP + p];
            float q[CS], k[CS], v[CS];
#pragma unroll
            for (int o = 0; o < CS; o++) {
                float aq = bq[n * CS + o], ak = bk[n * CS + o], av = bv[n * CS + o];
#pragma unroll
                for (int c = 0; c < CS; c++) {
                    aq += Wq[(n * CS + o) * CS + c] * xv[c];
                    ak += Wk[(n * CS + o) * CS + c] * xv[c];
                    av += Wv[(n * CS + o) * CS + c] * xv[c];
                }
                q[o] = aq * (LOG2E / 64.0f);
                k[o] = ak;
                v[o] = av;
            }
#pragma unroll
            for (int o = 0; o < CS; o++) {
                g_qcT[n][o][p] = q[o];
                g_kcT[n][o][p] = k[o];
                g_vcT[n][o][p] = v[o];
            }
            build_mono(k, m);
#pragma unroll
            for (int pp = 0; pp < 34; pp++)
#pragma unroll
                for (int off = 16; off; off >>= 1)
                    m[pp] += __shfl_down_sync(0xffffffffu, m[pp], off);
            int w = tid >> 5, l = tid & 31;
            if (l == 0)
#pragma unroll
                for (int pp = 0; pp < 34; pp++) red[w][pp] = m[pp];
        }
        __syncthreads();
        if (tid < 34) {
            float s = 0.f;
#pragma unroll
            for (int w2 = 0; w2 < 8; w2++) s += red[w2][tid];
            g_Apart[bx][n][tid] = s * c_coef[tid];
        }
    } else {
        // ---- proj_global role: 288 threads = (o = tid%72, pg = tid/72)
        float* wt = dyn;                    // [3][72][72] transposed: wt[m][c][o]
        float* xs = dyn + 3 * CH * CH;      // [72][16]
        const float* Wsrc[3] = {WqG, WkG, WvG};
#pragma unroll
        for (int mm = 0; mm < 3; mm++) {
            const float* Ws = Wsrc[mm];
            for (int r = tid; r < CH * CH; r += 288) {
                int o = r / CH, c = r % CH;
                wt[mm * CH * CH + c * CH + o] = Ws[r];  // coalesced read
            }
        }
        int p0 = (bid - 288) * 16;
        {
            int c = tid >> 2, pp4 = (tid & 3) * 4;
            *(float4*)&xs[c * 16 + pp4] = *(const float4*)&x[c * NP + p0 + pp4];
        }
        __syncthreads();
        int o = tid % 72, pg = tid / 72;
        float aq[4], ak[4], av[4];
        float bqv = bqG[o], bkv = bkG[o], bvv = bvG[o];
#pragma unroll
        for (int t = 0; t < 4; t++) { aq[t] = bqv; ak[t] = bkv; av[t] = bvv; }
        for (int c = 0; c < CH; c++) {
            float wq = wt[0 * CH * CH + c * CH + o];
            float wk = wt[1 * CH * CH + c * CH + o];
            float wv = wt[2 * CH * CH + c * CH + o];
            float4 xv4 = *(const float4*)&xs[c * 16 + pg * 4];
            aq[0] += wq * xv4.x; aq[1] += wq * xv4.y; aq[2] += wq * xv4.z; aq[3] += wq * xv4.w;
            ak[0] += wk * xv4.x; ak[1] += wk * xv4.y; ak[2] += wk * xv4.z; ak[3] += wk * xv4.w;
            av[0] += wv * xv4.x; av[1] += wv * xv4.y; av[2] += wv * xv4.z; av[3] += wv * xv4.w;
        }
#pragma unroll
        for (int t = 0; t < 4; t++) {
            int p = p0 + pg * 4 + t;
            g_qg[p][o] = aq[t] * (LOG2E / 64.0f);
            g_kg[p][o] = ak[t];
            g_vg[p][o] = av[t];
        }
    }
}

// ---------------------------------------------------------------------------
// STAGE 2 (256 threads): blocks [0,144) = momVQZ (Z in regs + B partials);
// blocks [144,400) = global scores E[j][i] = exp2(q_j . k_i).
__global__ void k_stage2() {
    int bid = blockIdx.x;
    int tid = threadIdx.x;
    if (bid < 144) {
        // ---- momVQZ role: n = bid/8, j-segment = bid%8 (512 j's each)
        int n = bid >> 3, seg = bid & 7;
        __shared__ float As[34];
        __shared__ float red[8][4][35];
        if (tid < 34) {
            float s = 0.f;
#pragma unroll
            for (int sg = 0; sg < 16; sg++) s += g_Apart[sg][n][tid];
            As[tid] = s;
        }
        __syncthreads();
        int c = tid & 3;
        float acc[35];
#pragma unroll
        for (int p = 0; p < 35; p++) acc[p] = 0.f;
        for (int j = seg * 512 + (tid >> 2); j < seg * 512 + 512; j += 64) {
            float q[4];
#pragma unroll
            for (int cc = 0; cc < 4; cc++) q[cc] = g_qcT[n][cc][j];
            float m[34];
            build_mono(q, m);
            float z = (float)NP;
#pragma unroll
            for (int p = 0; p < 34; p++) z += m[p] * As[p];
            float v = g_vcT[n][c][j] * (1.0f / z);
            acc[0] += v;
#pragma unroll
            for (int p = 0; p < 34; p++) acc[1 + p] += v * m[p];
        }
#pragma unroll
        for (int p = 0; p < 35; p++)
#pragma unroll
            for (int off = 16; off >= 4; off >>= 1)
                acc[p] += __shfl_down_sync(0xffffffffu, acc[p], off);
        int w = tid >> 5, l = tid & 31;
        if (l < 4)
#pragma unroll
            for (int p = 0; p < 35; p++) red[w][l][p] = acc[p];
        __syncthreads();
        if (tid < 140) {
            int cc = tid / 35, p = tid % 35;
            float s = 0.f;
#pragma unroll
            for (int w2 = 0; w2 < 8; w2++) s += red[w2][cc][p];
            g_Bpart[seg][n][cc][p] = s;
        }
    } else {
        // ---- score role: 256 i's per block, j-segment of 256.
        __shared__ __align__(16) float q_s[64][CH];
        int sb = bid - 144;                    // 0..255
        int ib = sb & 15, seg = sb >> 4;       // 16 i-blocks x 16 j-segs
        int i = ib * 256 + tid;
        ull kk2[CH / 2];
        const ulonglong2* krow = (const ulonglong2*)&g_kg[i][0];
#pragma unroll
        for (int c = 0; c < CH / 4; c++) { ulonglong2 t = krow[c]; kk2[2 * c] = t.x; kk2[2 * c + 1] = t.y; }
        for (int jt = 0; jt < 4; jt++) {
            int j0 = seg * 256 + jt * 64;
            const float4* qsrc = (const float4*)&g_qg[j0][0];
            float4* qdst = (float4*)&q_s[0][0];
            for (int r = tid; r < 64 * CH / 4; r += 256) qdst[r] = qsrc[r];
            __syncthreads();
#pragma unroll 2
            for (int j = 0; j < 64; j++) {
                const ulonglong2* qr = (const ulonglong2*)&q_s[j][0];
                ull s0 = 0, s1 = 0, s2 = 0, s3 = 0;
#pragma unroll
                for (int c = 0; c < CH / 4; c += 2) {
                    ulonglong2 t0 = qr[c], t1 = qr[c + 1];
                    s0 = pfma(kk2[2 * c], t0.x, s0);     s1 = pfma(kk2[2 * c + 1], t0.y, s1);
                    s2 = pfma(kk2[2 * c + 2], t1.x, s2); s3 = pfma(kk2[2 * c + 3], t1.y, s3);
                }
                float2 sf = unpack2(padd(padd(s0, s1), padd(s2, s3)));
                g_E[j0 + j][i] = fexp2(sf.x + sf.y);
            }
            __syncthreads();
        }
    }
}

// ---------------------------------------------------------------------------
// Row-sum E -> Z_j, fold 1/Z into vg. Warp per row, 8 rows per block.
__global__ void k_rowsum_fold() {
    int w = threadIdx.x >> 5, l = threadIdx.x & 31;
    int j = blockIdx.x * 8 + w;
    float z = 0.f;
    for (int t = l; t < NP / 4; t += 32) {
        float4 e4 = *(const float4*)&g_E[j][t * 4];
        z += (e4.x + e4.y) + (e4.z + e4.w);
    }
#pragma unroll
    for (int off = 16; off; off >>= 1) z += __shfl_down_sync(0xffffffffu, z, off);
    float rz = __shfl_sync(0xffffffffu, 1.0f / z, 0);
    if (l < CH / 4) {
        float4 v = *(float4*)&g_vg[j][l * 4];
        v.x *= rz; v.y *= rz; v.z *= rz; v.w *= rz;
        *(float4*)&g_vg[j][l * 4] = v;
    }
}

// ---------------------------------------------------------------------------
// Global pass 2 with memoized scores: out[c,i] += sum_{j in seg} v'[c,j]*E[j][i].
__global__ void __launch_bounds__(128) k_og2() {
    __shared__ __align__(16) float v_s[64][CH];
    int i = blockIdx.x * 128 + threadIdx.x;
    int seg = blockIdx.y;
    ull out2[CH / 2];
#pragma unroll
    for (int c = 0; c < CH / 2; c++) out2[c] = 0;
    for (int jt = 0; jt < 4; jt++) {
        int j0 = seg * 256 + jt * 64;
        const float4* vsrc = (const float4*)&g_vg[j0][0];
        float4* vdst = (float4*)&v_s[0][0];
        for (int r = threadIdx.x; r < 64 * CH / 4; r += 128) vdst[r] = vsrc[r];
        __syncthreads();
#pragma unroll 2
        for (int j = 0; j < 64; j++) {
            float e = __ldg(&g_E[j0 + j][i]);
            ull ee = pack2(e, e);
            const ulonglong2* vr = (const ulonglong2*)&v_s[j][0];
#pragma unroll
            for (int c = 0; c < CH / 4; c++) {
                ulonglong2 t = vr[c];
                out2[2 * c] = pfma(t.x, ee, out2[2 * c]);
                out2[2 * c + 1] = pfma(t.y, ee, out2[2 * c + 1]);
            }
        }
        __syncthreads();
    }
#pragma unroll
    for (int c = 0; c < CH / 4; c++) {
        float2 a = unpack2(out2[2 * c]), b = unpack2(out2[2 * c + 1]);
        *(float4*)&g_outGPart[seg][i][4 * c] = make_float4(a.x, a.y, b.x, b.y);
    }
}

// ---------------------------------------------------------------------------
// Chunk pass 2 via B-moments + 16 global partials + pooled reduction.
__global__ void k_apply(const float* __restrict__ x, float* __restrict__ out) {
    __shared__ float Bs[4][35];
    int n = blockIdx.y;
    int i = blockIdx.x * 256 + threadIdx.x;
    if (threadIdx.x < 140) {
        int cc = threadIdx.x / 35, p = threadIdx.x % 35;
        float s = 0.f;
#pragma unroll
        for (int sg = 0; sg < 8; sg++) s += g_Bpart[sg][n][cc][p];
        Bs[cc][p] = s;
    }
    __syncthreads();
    float k[4];
#pragma unroll
    for (int c = 0; c < 4; c++) k[c] = g_kcT[n][c][i];
    float m[34];
    build_mono(k, m);
#pragma unroll
    for (int p = 0; p < 34; p++) m[p] *= c_coef[p];
    float a[4];
#pragma unroll
    for (int c = 0; c < 4; c++) {
        float s = Bs[c][0];
#pragma unroll
        for (int p = 0; p < 34; p++) s += m[p] * Bs[c][1 + p];
        a[c] = s;
    }
#pragma unroll
    for (int sg = 0; sg < 16; sg++) {
        float4 og = *(const float4*)&g_outGPart[sg][i][n * 4];
        a[0] += og.x; a[1] += og.y; a[2] += og.z; a[3] += og.w;
    }
    float p = a[0] * x[(n * 4 + 0) * NP + i] + a[1] * x[(n * 4 + 1) * NP + i] +
              a[2] * x[(n * 4 + 2) * NP + i] + a[3] * x[(n * 4 + 3) * NP + i];
    out[n * NP + i] = p;
}

// ---------------------------------------------------------------------------
extern "C" void kernel_launch(void* const* d_in, const int* in_sizes, int n_in,
                              void* d_out, int out_size) {
    const float* x   = (const float*)d_in[0];
    const float* Wq  = (const float*)d_in[1];
    const float* bq  = (const float*)d_in[2];
    const float* Wk  = (const float*)d_in[3];
    const float* bk  = (const float*)d_in[4];
    const float* Wv  = (const float*)d_in[5];
    const float* bv  = (const float*)d_in[6];
    const float* WqG = (const float*)d_in[7];
    const float* bqG = (const float*)d_in[8];
    const float* WkG = (const float*)d_in[9];
    const float* bkG = (const float*)d_in[10];
    const float* WvG = (const float*)d_in[11];
    const float* bvG = (const float*)d_in[12];
    float* out = (float*)d_out;

    const int dynsmem = (3 * CH * CH + CH * 16) * (int)sizeof(float);  // ~66.8 KB
    static int attr_set = 0;
    if (!attr_set) {
        cudaFuncSetAttribute(k_stage1, cudaFuncAttributeMaxDynamicSharedMemorySize, dynsmem);
        attr_set = 1;
    }
    k_stage1<<<544, 288, dynsmem>>>(x, Wq, bq, Wk, bk, Wv, bv,
                                    WqG, bqG, WkG, bkG, WvG, bvG);
    k_stage2<<<400, 256>>>();
    k_rowsum_fold<<<512, 256>>>();
    k_og2<<<dim3(32, 16), 128>>>();
    k_apply<<<dim3(16, 18), 256>>>(x, out);
}